// round 8
// baseline (speedup 1.0000x reference)
#include <cuda_runtime.h>
#include <cstdint>

typedef unsigned long long u64;

#define Bn   16
#define R    360
#define RPAD 384   // padded row length (float2 units) for u/v scratch

// Scratch: u2[b][dpair k][i] = (u[i][2k], u[i][2k+1]) packed fp32x2; same for v (v includes +b_out)
// __device__ globals are zero-initialized; pad [360,384) stays zero (k1 never writes it).
__device__ u64 g_u2[Bn * 32 * RPAD];
__device__ u64 g_v2[Bn * 32 * RPAD];

// ---------- packed fp32x2 helpers (sm_100+) ----------
__device__ __forceinline__ u64 pack2(float x, float y) {
    u64 d; asm("mov.b64 %0, {%1, %2};" : "=l"(d) : "f"(x), "f"(y)); return d;
}
__device__ __forceinline__ void unpack2(u64 a, float &x, float &y) {
    asm("mov.b64 {%0, %1}, %2;" : "=f"(x), "=f"(y) : "l"(a));
}
__device__ __forceinline__ void ffma2(u64 &d, u64 a, u64 b) {
    asm("fma.rn.f32x2 %0, %1, %2, %0;" : "+l"(d) : "l"(a), "l"(b));
}
// acc += w * relu(u+v)
__device__ __forceinline__ void relu_dot2(u64 &acc, u64 u, u64 v, u64 w) {
    u64 s;
    asm("add.rn.f32x2 %0, %1, %2;" : "=l"(s) : "l"(u), "l"(v));
    float lo, hi; unpack2(s, lo, hi);
    lo = fmaxf(lo, 0.0f); hi = fmaxf(hi, 0.0f);
    s = pack2(lo, hi);
    ffma2(acc, s, w);
}

// ============================================================================
// Kernel 1: u = x @ Wout[0:64], v = x @ Wout[64:128] + b_out  (R2-proven)
// ============================================================================
#define K1_ROWS 48

__global__ __launch_bounds__(256, 2) void k1_uv(
    const float* __restrict__ x,      // [5760][64]
    const float* __restrict__ Wout,   // [128][64]
    const float* __restrict__ bout)   // [64]
{
    __shared__ u64 xs[32][K1_ROWS];  // [kpair][row]
    __shared__ u64 Wu[32][64];       // [kpair][d]
    __shared__ u64 Wv[32][64];

    const int t = threadIdx.x;
    const int row0 = blockIdx.x * K1_ROWS;

    {
        const u64* x2 = (const u64*)x;   // float2 view (32 per row)
        #pragma unroll
        for (int idx = t; idx < 32 * K1_ROWS; idx += 256) {
            const int p = idx / K1_ROWS;
            const int i = idx - p * K1_ROWS;
            xs[p][i] = x2[(row0 + i) * 32 + p];
        }
    }
    {
        const int c = t & 63, p0 = t >> 6;
        #pragma unroll
        for (int p = p0; p < 32; p += 4) {
            Wu[p][c] = pack2(Wout[(2 * p) * 64 + c],      Wout[(2 * p + 1) * 64 + c]);
            Wv[p][c] = pack2(Wout[(64 + 2 * p) * 64 + c], Wout[(65 + 2 * p) * 64 + c]);
        }
    }
    __syncthreads();

    const int rt = t & 15;
    const int ct = t >> 4;
    const int ccol = (ct & 7) * 8;
    const bool isv = (ct >= 8);
    const u64 (*Ws)[64] = isv ? Wv : Wu;

    u64 acc[3][8];
    #pragma unroll
    for (int ii = 0; ii < 3; ii++)
        #pragma unroll
        for (int j = 0; j < 8; j++) acc[ii][j] = 0ull;

    #pragma unroll 8
    for (int p = 0; p < 32; p++) {
        u64 xv[3];
        #pragma unroll
        for (int ii = 0; ii < 3; ii++) xv[ii] = xs[p][rt + 16 * ii];
        u64 wv[8];
        #pragma unroll
        for (int q = 0; q < 4; q++) {
            ulonglong2 w2 = *(const ulonglong2*)&Ws[p][ccol + 2 * q];
            wv[2 * q] = w2.x; wv[2 * q + 1] = w2.y;
        }
        #pragma unroll
        for (int ii = 0; ii < 3; ii++)
            #pragma unroll
            for (int j = 0; j < 8; j++)
                ffma2(acc[ii][j], xv[ii], wv[j]);
    }

    u64* gdst = isv ? g_v2 : g_u2;
    #pragma unroll
    for (int ii = 0; ii < 3; ii++) {
        const int grow = row0 + rt + 16 * ii;
        const int bb = grow / 360;
        const int i = grow - bb * 360;
        #pragma unroll
        for (int j = 0; j < 8; j += 2) {
            float l0, h0, l1, h1;
            unpack2(acc[ii][j], l0, h0);
            unpack2(acc[ii][j + 1], l1, h1);
            float v0 = l0 + h0, v1 = l1 + h1;
            const int dd = ccol + j;
            if (isv) { v0 += __ldg(&bout[dd]); v1 += __ldg(&bout[dd + 1]); }
            gdst[(bb * 32 + (dd >> 1)) * RPAD + i] = pack2(v0, v1);
        }
    }
}

// ============================================================================
// Kernel 2: out[b,rec,send] = relu( sum_d Wcat[d]*relu(u[send,d]+v[rec,d]) + b_cat )
// 64 send x 32 rec tile, 256 threads, 2 sends x 4 recs = 8 cells/thread.
// Manually software-pipelined k-loop (double-buffered LDS), fully unrolled.
// Live regs ~46 -> room for lookahead under the (256,4) = ~63-reg cap.
// ============================================================================
__global__ __launch_bounds__(256, 4) void k2_pair(
    const float* __restrict__ Wcat,   // [64]
    const float* __restrict__ bcat,   // [1]
    float* __restrict__ out)          // [16*360*360]
{
    __shared__ u64 Us[32][64];    // [dpair][send]
    __shared__ u64 Vs[32][32];    // [dpair][rec]
    __shared__ u64 Ww[32];        // packed Wcat pairs

    const int t = threadIdx.x;
    const int b  = blockIdx.z;
    const int s0 = blockIdx.x * 64;
    const int r0 = blockIdx.y * 32;

    // Fill tiles (coalesced; pad region reads zeros)
    {
        const int c = t & 63, k0 = t >> 6;
        const u64* gu = g_u2 + b * 32 * RPAD + s0 + c;
        #pragma unroll
        for (int k = k0; k < 32; k += 4) Us[k][c] = gu[k * RPAD];

        const int cv = t & 31, kv0 = t >> 5;
        const u64* gv = g_v2 + b * 32 * RPAD + r0 + cv;
        #pragma unroll
        for (int k = kv0; k < 32; k += 8) Vs[k][cv] = gv[k * RPAD];

        if (t < 32) Ww[t] = ((const u64*)Wcat)[t];
    }
    __syncthreads();

    const int lane = t & 31;       // sends 2*lane, 2*lane+1 (conflict-free LDS.128)
    const int wg   = t >> 5;       // recs 4*wg .. 4*wg+3 (broadcast LDS.128)

    u64 acc[4][2];
    #pragma unroll
    for (int i = 0; i < 4; i++) { acc[i][0] = 0ull; acc[i][1] = 0ull; }

    // Software pipeline: prefetch k=0
    u64 w2 = Ww[0];
    ulonglong2 ua = *(const ulonglong2*)&Us[0][2 * lane];
    ulonglong2 va = *(const ulonglong2*)&Vs[0][4 * wg];
    ulonglong2 vb = *(const ulonglong2*)&Vs[0][4 * wg + 2];

    #pragma unroll
    for (int k = 0; k < 32; k++) {
        const u64 w2c = w2;
        const u64 u0 = ua.x, u1 = ua.y;
        const u64 v0 = va.x, v1 = va.y, v2 = vb.x, v3 = vb.y;
        if (k < 31) {                       // prefetch k+1 before the math
            w2 = Ww[k + 1];
            ua = *(const ulonglong2*)&Us[k + 1][2 * lane];
            va = *(const ulonglong2*)&Vs[k + 1][4 * wg];
            vb = *(const ulonglong2*)&Vs[k + 1][4 * wg + 2];
        }
        relu_dot2(acc[0][0], u0, v0, w2c);  relu_dot2(acc[0][1], u1, v0, w2c);
        relu_dot2(acc[1][0], u0, v1, w2c);  relu_dot2(acc[1][1], u1, v1, w2c);
        relu_dot2(acc[2][0], u0, v2, w2c);  relu_dot2(acc[2][1], u1, v2, w2c);
        relu_dot2(acc[3][0], u0, v3, w2c);  relu_dot2(acc[3][1], u1, v3, w2c);
    }

    // Epilogue: lo+hi + b_cat, relu, float2 stores (256B coalesced per rec row)
    const float bc = __ldg(bcat);
    const int s = s0 + 2 * lane;
    if (s < R) {
        #pragma unroll
        for (int i = 0; i < 4; i++) {
            const int rec = r0 + 4 * wg + i;
            if (rec < R) {
                float l0, h0, l1, h1;
                unpack2(acc[i][0], l0, h0);
                unpack2(acc[i][1], l1, h1);
                float2 o;
                o.x = fmaxf(l0 + h0 + bc, 0.0f);
                o.y = fmaxf(l1 + h1 + bc, 0.0f);
                *(float2*)&out[((size_t)(b * R + rec)) * R + s] = o;
            }
        }
    }
}

extern "C" void kernel_launch(void* const* d_in, const int* in_sizes, int n_in,
                              void* d_out, int out_size) {
    (void)in_sizes; (void)n_in; (void)out_size;
    const float* x    = (const float*)d_in[0];  // (16,360,64)
    const float* Wout = (const float*)d_in[1];  // (128,64)
    const float* bout = (const float*)d_in[2];  // (64)
    const float* Wcat = (const float*)d_in[3];  // (64,1)
    const float* bcat = (const float*)d_in[4];  // (1)
    float* out = (float*)d_out;                 // (16,360,360,1) fp32

    k1_uv<<<120, 256>>>(x, Wout, bout);                    // 5760 rows / 48
    k2_pair<<<dim3(6, 12, 16), 256>>>(Wcat, bcat, out);    // 6 send x 12 rec x 16 batch
}